// round 16
// baseline (speedup 1.0000x reference)
#include <cuda_runtime.h>
#include <cuda_fp16.h>
#include <cstdint>
#include <cstddef>

#define TLEN  512
#define BATCH 128
#define EDIM  128
#define HDIM  128
#define GDIM  512   // 4*H
#define VOCAB 100000

// Scratch (device globals — no allocation).
// xp layout: [dir][t][slice(16)][g(512)][8b]  fp16
static __device__ __half g_xp[(size_t)2 * TLEN * 16 * GDIM * 8];
static __device__ float g_pool[2 * BATCH * HDIM];
static __device__ int   g_flagc[2][TLEN / 4];   // proj completion, 16 tiles per 4-t chunk
static __device__ int   g_prog[2];              // scan progress (chunk index), per dir

// ---------- helpers ----------
#define H_HALF2 0x38003800u   // {0.5,0.5} fp16
__device__ __forceinline__ unsigned hmul2(unsigned a, unsigned b) {
    unsigned d; asm("mul.rn.f16x2 %0,%1,%2;" : "=r"(d) : "r"(a), "r"(b)); return d;
}
__device__ __forceinline__ unsigned hadd2u(unsigned a, unsigned b) {
    unsigned d; asm("add.rn.f16x2 %0,%1,%2;" : "=r"(d) : "r"(a), "r"(b)); return d;
}
__device__ __forceinline__ unsigned hfma2(unsigned a, unsigned b, unsigned c) {
    unsigned d; asm("fma.rn.f16x2 %0,%1,%2,%3;" : "=r"(d) : "r"(a), "r"(b), "r"(c)); return d;
}
__device__ __forceinline__ unsigned htanh2(unsigned a) {
    unsigned d; asm("tanh.approx.f16x2 %0,%1;" : "=r"(d) : "r"(a)); return d;
}
__device__ __forceinline__ unsigned hsig2(unsigned x) {   // 0.5*tanh(0.5x)+0.5
    return hfma2(htanh2(hmul2(x, H_HALF2)), H_HALF2, H_HALF2);
}
__device__ __forceinline__ unsigned hmax2u(unsigned a, unsigned b) {
    __half2 r = __hmax2(*(__half2*)&a, *(__half2*)&b);
    return *(unsigned*)&r;
}
__device__ __forceinline__ float2 h22f2(unsigned v) {
    return __half22float2(*(__half2*)&v);
}
__device__ __forceinline__ unsigned dup_h2(float v) {
    __half2 h = __half2half2(__float2half_rn(v));
    return *(unsigned*)&h;
}
__device__ __forceinline__ unsigned pkh2(float lo, float hi) {
    __half2 h = __floats2half2_rn(lo, hi);
    return *(unsigned*)&h;
}
__device__ __forceinline__ unsigned sptr(const void* p) {
    return (unsigned)__cvta_generic_to_shared(p);
}
__device__ __forceinline__ int ld_acq(const int* p) {
    int v; asm volatile("ld.acquire.gpu.global.s32 %0,[%1];" : "=r"(v) : "l"(p)); return v;
}
__device__ __forceinline__ int ld_vol(const int* p) { return *(volatile const int*)p; }
__device__ __forceinline__ void mmaf16(unsigned& d0, unsigned& d1,
                                       unsigned a0, unsigned a1, unsigned a2, unsigned a3,
                                       unsigned b0, unsigned b1) {
    asm("mma.sync.aligned.m16n8k16.row.col.f16.f16.f16.f16 "
        "{%0,%1},{%2,%3,%4,%5},{%6,%7},{%0,%1};"
        : "+r"(d0), "+r"(d1)
        : "r"(a0), "r"(a1), "r"(a2), "r"(a3), "r"(b0), "r"(b1));
}
__device__ __forceinline__ void ldsm4(unsigned& r0, unsigned& r1, unsigned& r2, unsigned& r3,
                                      unsigned addr) {
    asm volatile("ldmatrix.sync.aligned.m8n8.x4.shared.b16 {%0,%1,%2,%3}, [%4];"
                 : "=r"(r0), "=r"(r1), "=r"(r2), "=r"(r3) : "r"(addr));
}
__device__ __forceinline__ void ldsm4t(unsigned& r0, unsigned& r1, unsigned& r2, unsigned& r3,
                                       unsigned addr) {
    asm volatile("ldmatrix.sync.aligned.m8n8.x4.trans.shared.b16 {%0,%1,%2,%3}, [%4];"
                 : "=r"(r0), "=r"(r1), "=r"(r2), "=r"(r3) : "r"(addr));
}

// =====================================================================
// MEGA kernel: blocks 0-31 = persistent scan CTAs (2 dir x 16 slices);
// blocks 32..4127 = proj tiles (t-major, dirs interleaved), rate-limited
// to <= 8 chunks ahead of the scan to keep clocks high / HBM quiet.
// =====================================================================
#define PJ_STRIDE 136
#define SC_WSTRIDE 136
#define SC_SMEM (512 * SC_WSTRIDE * 2)   // 139264 B dynamic (covers proj's 69632 too)

__global__ void __launch_bounds__(256, 1) mega_kernel(
    const int* __restrict__ x, const float* __restrict__ table,
    const float* __restrict__ Wih_f, const float* __restrict__ Wih_b,
    const float* __restrict__ Whh_f, const float* __restrict__ Whh_b,
    const float* __restrict__ bih_f, const float* __restrict__ bhh_f,
    const float* __restrict__ bih_b, const float* __restrict__ bhh_b)
{
    extern __shared__ char dynsm[];
    const int tid = threadIdx.x, lane = tid & 31, w = tid >> 5;
    const int bid = blockIdx.x;

    if (bid >= 32) {
        // ================= PROJ ROLE =================
        __half* Wsm = (__half*)dynsm;             // [128][136]
        __half* Esm = Wsm + 128 * PJ_STRIDE;      // [128][136]
        __shared__ float bias_s[128];
        __shared__ int   tok_s[128];

        const int pbid  = bid - 32;
        const int gtile = pbid & 3;
        const int tt    = pbid >> 2;
        const int dir   = tt & 1;                 // dirs interleaved, t ascending
        const int t     = tt >> 1;
        const float* bi = dir ? bih_b : bih_f;
        const float* bh = dir ? bhh_b : bhh_f;
        const int tsrc  = dir ? (TLEN - 1 - t) : t;

        // backpressure: stay <= 8 chunks ahead of this dir's scan
        if (tid == 0) {
            const int chunk = t >> 2;
            while (chunk > ld_vol(&g_prog[dir]) + 8) __nanosleep(1000);
        }
        __syncthreads();

        if (tid < 128) {
            const int gg = gtile * 128 + tid;
            bias_s[tid] = bi[gg] + bh[gg];
            tok_s[tid] = x[tid * TLEN + tsrc];
        }
        __syncthreads();

        // W rows: f32 -> f16 inline (L2-hot across t-tiles)
        const float* wsrc = (dir ? Wih_b : Wih_f) + (size_t)(gtile * 128) * EDIM;
        #pragma unroll
        for (int it = 0; it < 16; ++it) {
            const int idx = it * 256 + tid;
            const int rg = idx >> 5, q = idx & 31;
            const float4 v = __ldg((const float4*)(wsrc + (size_t)rg * EDIM) + q);
            *(uint2*)&Wsm[rg * PJ_STRIDE + q * 4] =
                make_uint2(pkh2(v.x, v.y), pkh2(v.z, v.w));
        }
        // E rows: gather f32 table rows by token, convert inline
        #pragma unroll
        for (int it = 0; it < 16; ++it) {
            const int idx = it * 256 + tid;
            const int rb = idx >> 5, q = idx & 31;
            const float4 v = __ldg((const float4*)(table + (size_t)tok_s[rb] * EDIM) + q);
            *(uint2*)&Esm[rb * PJ_STRIDE + q * 4] =
                make_uint2(pkh2(v.x, v.y), pkh2(v.z, v.w));
        }
        __syncthreads();

        const int li = lane & 7, grp = lane >> 3;
        const int wg = w & 3, wb = w >> 2;
        const int gbase = wg * 32;
        const int row = lane >> 2, kq = (lane & 3) * 2;

        unsigned D[2][8][2];
        #pragma unroll
        for (int m = 0; m < 2; ++m) {
            const unsigned hb0 = dup_h2(bias_s[gbase + m * 16 + row]);
            const unsigned hb1 = dup_h2(bias_s[gbase + m * 16 + row + 8]);
            #pragma unroll
            for (int nt = 0; nt < 8; ++nt) { D[m][nt][0] = hb0; D[m][nt][1] = hb1; }
        }

        #pragma unroll
        for (int p = 0; p < 4; ++p) {
            unsigned A[2][2][4];
            #pragma unroll
            for (int m = 0; m < 2; ++m) {
                const unsigned abase = sptr(Wsm) +
                    (((gbase + m * 16 + (grp & 1) * 8 + li) * PJ_STRIDE + (grp >> 1) * 8) << 1);
                ldsm4(A[m][0][0], A[m][0][1], A[m][0][2], A[m][0][3], abase + (2 * p) * 32);
                ldsm4(A[m][1][0], A[m][1][1], A[m][1][2], A[m][1][3], abase + (2 * p + 1) * 32);
            }
            #pragma unroll
            for (int nt = 0; nt < 8; ++nt) {
                unsigned b0a, b1a, b0b, b1b;
                const unsigned eb = sptr(Esm) +
                    (((wb * 64 + nt * 8 + li) * PJ_STRIDE + grp * 8) << 1) + p * 64;
                ldsm4(b0a, b1a, b0b, b1b, eb);
                #pragma unroll
                for (int m = 0; m < 2; ++m) {
                    mmaf16(D[m][nt][0], D[m][nt][1],
                           A[m][0][0], A[m][0][1], A[m][0][2], A[m][0][3], b0a, b1a);
                    mmaf16(D[m][nt][0], D[m][nt][1],
                           A[m][1][0], A[m][1][1], A[m][1][2], A[m][1][3], b0b, b1b);
                }
            }
        }

        __half* base = g_xp + (size_t)(dir * TLEN + t) * 16 * GDIM * 8;
        #pragma unroll
        for (int m = 0; m < 2; ++m) {
            const int gg0 = gtile * 128 + gbase + m * 16 + row;
            #pragma unroll
            for (int nt = 0; nt < 8; ++nt) {
                const int slice = wb * 8 + nt;
                __half* o = base + ((size_t)slice * GDIM) * 8 + kq;
                *(unsigned*)(o + (size_t)gg0 * 8)       = D[m][nt][0];
                *(unsigned*)(o + (size_t)(gg0 + 8) * 8) = D[m][nt][1];
            }
        }

        __threadfence();
        __syncthreads();
        if (tid == 0) atomicAdd(&g_flagc[dir][t >> 2], 1);
        return;
    }

    // ================= SCAN ROLE =================
    {
        __half* Wsm = (__half*)dynsm;   // [512][136]
        __shared__ __align__(16) __half h_pp[2][HDIM][8];

        const int dir   = bid >> 4;
        const int slice = bid & 15;
        const float* Whh = dir ? Whh_b : Whh_f;

        #pragma unroll 4
        for (int it = 0; it < 64; ++it) {
            const int idx = it * 256 + tid;
            const int rw = idx >> 5, q = idx & 31;
            const float4 v = __ldg((const float4*)(Whh + (size_t)rw * HDIM) + q);
            *(uint2*)&Wsm[rw * SC_WSTRIDE + q * 4] =
                make_uint2(pkh2(v.x, v.y), pkh2(v.z, v.w));
        }
        for (int i = tid; i < 2 * HDIM * 8; i += 256) ((__half*)h_pp)[i] = __float2half(0.f);
        __syncthreads();

        const int li = lane & 7, grp = lane >> 3;
        unsigned A[4][8][4];
        #pragma unroll
        for (int q = 0; q < 4; ++q) {
            const unsigned base = sptr(Wsm) +
                (((q * 128 + w * 16 + (grp & 1) * 8 + li) * SC_WSTRIDE + (grp >> 1) * 8) << 1);
            #pragma unroll
            for (int kt = 0; kt < 8; ++kt)
                ldsm4(A[q][kt][0], A[q][kt][1], A[q][kt][2], A[q][kt][3], base + kt * 32);
        }

        const int ur = w * 16 + (lane >> 2);
        const int cb = (lane & 3) * 2;
        const __half* xpd = g_xp + (size_t)dir * TLEN * 16 * GDIM * 8;
        size_t off[4];
        #pragma unroll
        for (int q = 0; q < 4; ++q)
            off[q] = ((size_t)slice * GDIM + q * 128 + ur) * 8 + cb;

        while (ld_acq(&g_flagc[dir][0]) < 16) __nanosleep(200);

        unsigned px0[4], px1[4];
        #pragma unroll
        for (int q = 0; q < 4; ++q) {
            px0[q] = *(const unsigned*)(xpd + off[q]);
            px1[q] = *(const unsigned*)(xpd + off[q] + 64);
        }

        unsigned c20 = 0u, c21 = 0u;
        unsigned hm0 = 0xFC00FC00u, hm1 = 0xFC00FC00u;

        #define GATE_MMA(q, p0, p1) do {                                          \
            unsigned d0 = px0c[q], d1 = px1c[q], e0 = 0u, e1 = 0u;                \
            _Pragma("unroll")                                                     \
            for (int kt = 0; kt < 4; ++kt) {                                      \
                mmaf16(d0, d1, A[q][kt][0], A[q][kt][1], A[q][kt][2], A[q][kt][3],\
                       B[kt][0], B[kt][1]);                                       \
                mmaf16(e0, e1, A[q][kt+4][0], A[q][kt+4][1], A[q][kt+4][2],       \
                       A[q][kt+4][3], B[kt+4][0], B[kt+4][1]);                    \
            }                                                                     \
            p0 = hadd2u(d0, e0); p1 = hadd2u(d1, e1);                             \
        } while (0)

        for (int t = 0; t < TLEN; ++t) {
            if ((t & 15) == 0) {
                if (slice == 0 && tid == 0)
                    *(volatile int*)&g_prog[dir] = t >> 2;
                // gate chunks (t>>2)+1 .. +4 (covers prefetches through t+16);
                // 4 acquire loads issued back-to-back so latencies overlap.
                const int c0 = (t >> 2) + 1;
                const int k0 = c0 < 128 ? c0 : 127;
                const int k1 = c0 + 1 < 128 ? c0 + 1 : 127;
                const int k2 = c0 + 2 < 128 ? c0 + 2 : 127;
                const int k3 = c0 + 3 < 128 ? c0 + 3 : 127;
                for (;;) {
                    const int f0 = ld_acq(&g_flagc[dir][k0]);
                    const int f1 = ld_acq(&g_flagc[dir][k1]);
                    const int f2 = ld_acq(&g_flagc[dir][k2]);
                    const int f3 = ld_acq(&g_flagc[dir][k3]);
                    if (((f0 < f1 ? f0 : f1) < (f2 < f3 ? f2 : f3)
                             ? (f0 < f1 ? f0 : f1) : (f2 < f3 ? f2 : f3)) >= 16) break;
                    __nanosleep(300);
                }
            }

            unsigned B[8][2];
            const unsigned hbase = sptr(&h_pp[t & 1][0][0]) + lane * 16;
            #pragma unroll
            for (int j = 0; j < 4; ++j)
                ldsm4t(B[2*j][0], B[2*j][1], B[2*j+1][0], B[2*j+1][1], hbase + j * 512);

            unsigned px0c[4], px1c[4];
            #pragma unroll
            for (int q = 0; q < 4; ++q) { px0c[q] = px0[q]; px1c[q] = px1[q]; }

            const __half* xn = xpd + (size_t)((t + 1 < TLEN) ? t + 1 : t) * 16 * GDIM * 8;
            #pragma unroll
            for (int q = 0; q < 4; ++q) {
                px0[q] = *(const unsigned*)(xn + off[q]);
                px1[q] = *(const unsigned*)(xn + off[q] + 64);
            }

            // gate-sequential: each gate's activation hides under next gate's mma
            unsigned p0, p1;
            GATE_MMA(2, p0, p1);                       // g first
            const unsigned G0 = htanh2(p0), G1 = htanh2(p1);
            GATE_MMA(0, p0, p1);                       // i
            const unsigned I0 = hsig2(p0), I1 = hsig2(p1);
            GATE_MMA(1, p0, p1);                       // f
            const unsigned F0 = hsig2(p0), F1 = hsig2(p1);
            c20 = hfma2(F0, c20, hmul2(I0, G0));       // c + tanh(c) hide under o's mma
            c21 = hfma2(F1, c21, hmul2(I1, G1));
            const unsigned T0 = htanh2(c20), T1 = htanh2(c21);
            GATE_MMA(3, p0, p1);                       // o
            const unsigned O0 = hsig2(p0), O1 = hsig2(p1);
            const unsigned H0 = hmul2(O0, T0);
            const unsigned H1 = hmul2(O1, T1);

            __half* hw = &h_pp[(t + 1) & 1][0][0];
            *(unsigned*)&hw[ur * 8 + cb]       = H0;
            *(unsigned*)&hw[(ur + 8) * 8 + cb] = H1;
            hm0 = hmax2u(hm0, H0);                     // off the barrier path
            hm1 = hmax2u(hm1, H1);
            __syncthreads();
        }
        #undef GATE_MMA

        const float2 m0 = h22f2(hm0), m1 = h22f2(hm1);
        const int bb = slice * 8;
        g_pool[((size_t)dir * BATCH + bb + cb)     * HDIM + ur]     = m0.x;
        g_pool[((size_t)dir * BATCH + bb + cb + 1) * HDIM + ur]     = m0.y;
        g_pool[((size_t)dir * BATCH + bb + cb)     * HDIM + ur + 8] = m1.x;
        g_pool[((size_t)dir * BATCH + bb + cb + 1) * HDIM + ur + 8] = m1.y;
    }
}

// =====================================================================
// Kernel 2: MLP head + flag reset for next replay (graph-replay safe:
// globals start zeroed; every launch ends with flags reset).
// =====================================================================
__global__ void __launch_bounds__(256) mlp_kernel(
    const float* __restrict__ W1, const float* __restrict__ b1,
    const float* __restrict__ W2, const float* __restrict__ b2,
    float* __restrict__ out)
{
    __shared__ __align__(16) float pv[256];
    __shared__ float red[64];
    const int b = blockIdx.x;
    const int tid = threadIdx.x;
    const int u = tid >> 2, p = tid & 3;

    if (b == 0) {                       // reset sync state for next replay
        ((int*)g_flagc)[tid] = 0;       // 2*128 ints
        if (tid < 2) g_prog[tid] = 0;
    }

    {
        const int dir = tid >> 7, uu = tid & 127;
        pv[tid] = g_pool[((size_t)dir * BATCH + b) * HDIM + uu];
    }
    __syncthreads();

    float acc = 0.f;
    const float4* w4 = (const float4*)(W1 + (size_t)u * 256 + p * 64);
    const float4* p4 = (const float4*)(pv + p * 64);
    #pragma unroll
    for (int k = 0; k < 16; ++k) {
        const float4 wv = w4[k], pvv = p4[k];
        acc += wv.x * pvv.x + wv.y * pvv.y + wv.z * pvv.z + wv.w * pvv.w;
    }
    acc += __shfl_down_sync(0xffffffffu, acc, 2, 4);
    acc += __shfl_down_sync(0xffffffffu, acc, 1, 4);
    if (p == 0) red[u] = fmaxf(acc + b1[u], 0.f) * W2[u];
    __syncthreads();

    if (tid < 32) {
        float s = red[tid] + red[tid + 32];
        #pragma unroll
        for (int d = 16; d > 0; d >>= 1) s += __shfl_down_sync(0xffffffffu, s, d);
        if (tid == 0) out[b] = 1.f / (1.f + expf(-(s + b2[0])));
    }
}

// =====================================================================
extern "C" void kernel_launch(void* const* d_in, const int* in_sizes, int n_in,
                              void* d_out, int out_size) {
    const int*   x     = (const int*)d_in[0];
    const float* table = (const float*)d_in[1];
    const float* Wih_f = (const float*)d_in[2];
    const float* Whh_f = (const float*)d_in[3];
    const float* bih_f = (const float*)d_in[4];
    const float* bhh_f = (const float*)d_in[5];
    const float* Wih_b = (const float*)d_in[6];
    const float* Whh_b = (const float*)d_in[7];
    const float* bih_b = (const float*)d_in[8];
    const float* bhh_b = (const float*)d_in[9];
    const float* W1    = (const float*)d_in[10];
    const float* b1    = (const float*)d_in[11];
    const float* W2    = (const float*)d_in[12];
    const float* b2    = (const float*)d_in[13];
    float* out = (float*)d_out;

    cudaFuncSetAttribute(mega_kernel, cudaFuncAttributeMaxDynamicSharedMemorySize, SC_SMEM);

    mega_kernel<<<32 + 4096, 256, SC_SMEM>>>(x, table, Wih_f, Wih_b, Whh_f, Whh_b,
                                             bih_f, bhh_f, bih_b, bhh_b);
    mlp_kernel<<<128, 256>>>(W1, b1, W2, b2, out);
}

// round 17
// speedup vs baseline: 1.1739x; 1.1739x over previous
#include <cuda_runtime.h>
#include <cuda_fp16.h>
#include <cstdint>
#include <cstddef>

#define TLEN  512
#define BATCH 128
#define EDIM  128
#define HDIM  128
#define GDIM  512   // 4*H
#define VOCAB 100000

// Scratch (device globals — no allocation).
// xp layout: [dir][t][slice(16)][g(512)][8b]  fp16
static __device__ __half g_xp[(size_t)2 * TLEN * 16 * GDIM * 8];
static __device__ float g_pool[2 * BATCH * HDIM];
static __device__ int   g_flagc[2][TLEN / 8];   // proj completion, 32 tiles per 8-t chunk
static __device__ int   g_prog[2];              // scan progress (8t-chunk index), per dir

// ---------- helpers ----------
#define H_HALF2 0x38003800u   // {0.5,0.5} fp16
__device__ __forceinline__ unsigned hmul2(unsigned a, unsigned b) {
    unsigned d; asm("mul.rn.f16x2 %0,%1,%2;" : "=r"(d) : "r"(a), "r"(b)); return d;
}
__device__ __forceinline__ unsigned hadd2u(unsigned a, unsigned b) {
    unsigned d; asm("add.rn.f16x2 %0,%1,%2;" : "=r"(d) : "r"(a), "r"(b)); return d;
}
__device__ __forceinline__ unsigned hfma2(unsigned a, unsigned b, unsigned c) {
    unsigned d; asm("fma.rn.f16x2 %0,%1,%2,%3;" : "=r"(d) : "r"(a), "r"(b), "r"(c)); return d;
}
__device__ __forceinline__ unsigned htanh2(unsigned a) {
    unsigned d; asm("tanh.approx.f16x2 %0,%1;" : "=r"(d) : "r"(a)); return d;
}
__device__ __forceinline__ unsigned hsig2(unsigned x) {   // 0.5*tanh(0.5x)+0.5
    return hfma2(htanh2(hmul2(x, H_HALF2)), H_HALF2, H_HALF2);
}
__device__ __forceinline__ unsigned hmax2u(unsigned a, unsigned b) {
    __half2 r = __hmax2(*(__half2*)&a, *(__half2*)&b);
    return *(unsigned*)&r;
}
__device__ __forceinline__ float2 h22f2(unsigned v) {
    return __half22float2(*(__half2*)&v);
}
__device__ __forceinline__ unsigned dup_h2(float v) {
    __half2 h = __half2half2(__float2half_rn(v));
    return *(unsigned*)&h;
}
__device__ __forceinline__ unsigned pkh2(float lo, float hi) {
    __half2 h = __floats2half2_rn(lo, hi);
    return *(unsigned*)&h;
}
__device__ __forceinline__ unsigned sptr(const void* p) {
    return (unsigned)__cvta_generic_to_shared(p);
}
__device__ __forceinline__ int ld_acq(const int* p) {
    int v; asm volatile("ld.acquire.gpu.global.s32 %0,[%1];" : "=r"(v) : "l"(p)); return v;
}
__device__ __forceinline__ int ld_vol(const int* p) { return *(volatile const int*)p; }
__device__ __forceinline__ void mmaf16(unsigned& d0, unsigned& d1,
                                       unsigned a0, unsigned a1, unsigned a2, unsigned a3,
                                       unsigned b0, unsigned b1) {
    asm("mma.sync.aligned.m16n8k16.row.col.f16.f16.f16.f16 "
        "{%0,%1},{%2,%3,%4,%5},{%6,%7},{%0,%1};"
        : "+r"(d0), "+r"(d1)
        : "r"(a0), "r"(a1), "r"(a2), "r"(a3), "r"(b0), "r"(b1));
}
__device__ __forceinline__ void ldsm4(unsigned& r0, unsigned& r1, unsigned& r2, unsigned& r3,
                                      unsigned addr) {
    asm volatile("ldmatrix.sync.aligned.m8n8.x4.shared.b16 {%0,%1,%2,%3}, [%4];"
                 : "=r"(r0), "=r"(r1), "=r"(r2), "=r"(r3) : "r"(addr));
}
__device__ __forceinline__ void ldsm4t(unsigned& r0, unsigned& r1, unsigned& r2, unsigned& r3,
                                       unsigned addr) {
    asm volatile("ldmatrix.sync.aligned.m8n8.x4.trans.shared.b16 {%0,%1,%2,%3}, [%4];"
                 : "=r"(r0), "=r"(r1), "=r"(r2), "=r"(r3) : "r"(addr));
}

// =====================================================================
// MEGA kernel: blocks 0-31 = persistent scan CTAs (2 dir x 16 slices);
// blocks 32..4127 = proj tiles (t-major, dirs interleaved), rate-limited
// to <= 4 chunks (of 8t) ahead of the scan.
// =====================================================================
#define PJ_STRIDE 136
#define SC_WSTRIDE 136
#define SC_SMEM (512 * SC_WSTRIDE * 2)   // 139264 B dynamic (covers proj's 69632 too)

__global__ void __launch_bounds__(256, 1) mega_kernel(
    const int* __restrict__ x, const float* __restrict__ table,
    const float* __restrict__ Wih_f, const float* __restrict__ Wih_b,
    const float* __restrict__ Whh_f, const float* __restrict__ Whh_b,
    const float* __restrict__ bih_f, const float* __restrict__ bhh_f,
    const float* __restrict__ bih_b, const float* __restrict__ bhh_b)
{
    extern __shared__ char dynsm[];
    const int tid = threadIdx.x, lane = tid & 31, w = tid >> 5;
    const int bid = blockIdx.x;

    if (bid >= 32) {
        // ================= PROJ ROLE =================
        __half* Wsm = (__half*)dynsm;             // [128][136]
        __half* Esm = Wsm + 128 * PJ_STRIDE;      // [128][136]
        __shared__ float bias_s[128];
        __shared__ int   tok_s[128];

        const int pbid  = bid - 32;
        const int gtile = pbid & 3;
        const int tt    = pbid >> 2;
        const int dir   = tt & 1;                 // dirs interleaved, t ascending
        const int t     = tt >> 1;
        const float* bi = dir ? bih_b : bih_f;
        const float* bh = dir ? bhh_b : bhh_f;
        const int tsrc  = dir ? (TLEN - 1 - t) : t;

        // backpressure: stay <= 4 chunks (8t each) ahead of this dir's scan
        if (tid == 0) {
            const int chunk = t >> 3;
            while (chunk > ld_vol(&g_prog[dir]) + 4) __nanosleep(1000);
        }
        __syncthreads();

        if (tid < 128) {
            const int gg = gtile * 128 + tid;
            bias_s[tid] = bi[gg] + bh[gg];
            tok_s[tid] = x[tid * TLEN + tsrc];
        }
        __syncthreads();

        // W rows: f32 -> f16 inline (L2-hot across t-tiles)
        const float* wsrc = (dir ? Wih_b : Wih_f) + (size_t)(gtile * 128) * EDIM;
        #pragma unroll
        for (int it = 0; it < 16; ++it) {
            const int idx = it * 256 + tid;
            const int rg = idx >> 5, q = idx & 31;
            const float4 v = __ldg((const float4*)(wsrc + (size_t)rg * EDIM) + q);
            *(uint2*)&Wsm[rg * PJ_STRIDE + q * 4] =
                make_uint2(pkh2(v.x, v.y), pkh2(v.z, v.w));
        }
        // E rows: gather f32 table rows by token, convert inline
        #pragma unroll
        for (int it = 0; it < 16; ++it) {
            const int idx = it * 256 + tid;
            const int rb = idx >> 5, q = idx & 31;
            const float4 v = __ldg((const float4*)(table + (size_t)tok_s[rb] * EDIM) + q);
            *(uint2*)&Esm[rb * PJ_STRIDE + q * 4] =
                make_uint2(pkh2(v.x, v.y), pkh2(v.z, v.w));
        }
        __syncthreads();

        const int li = lane & 7, grp = lane >> 3;
        const int wg = w & 3, wb = w >> 2;
        const int gbase = wg * 32;
        const int row = lane >> 2, kq = (lane & 3) * 2;

        unsigned D[2][8][2];
        #pragma unroll
        for (int m = 0; m < 2; ++m) {
            const unsigned hb0 = dup_h2(bias_s[gbase + m * 16 + row]);
            const unsigned hb1 = dup_h2(bias_s[gbase + m * 16 + row + 8]);
            #pragma unroll
            for (int nt = 0; nt < 8; ++nt) { D[m][nt][0] = hb0; D[m][nt][1] = hb1; }
        }

        #pragma unroll
        for (int p = 0; p < 4; ++p) {
            unsigned A[2][2][4];
            #pragma unroll
            for (int m = 0; m < 2; ++m) {
                const unsigned abase = sptr(Wsm) +
                    (((gbase + m * 16 + (grp & 1) * 8 + li) * PJ_STRIDE + (grp >> 1) * 8) << 1);
                ldsm4(A[m][0][0], A[m][0][1], A[m][0][2], A[m][0][3], abase + (2 * p) * 32);
                ldsm4(A[m][1][0], A[m][1][1], A[m][1][2], A[m][1][3], abase + (2 * p + 1) * 32);
            }
            #pragma unroll
            for (int nt = 0; nt < 8; ++nt) {
                unsigned b0a, b1a, b0b, b1b;
                const unsigned eb = sptr(Esm) +
                    (((wb * 64 + nt * 8 + li) * PJ_STRIDE + grp * 8) << 1) + p * 64;
                ldsm4(b0a, b1a, b0b, b1b, eb);
                #pragma unroll
                for (int m = 0; m < 2; ++m) {
                    mmaf16(D[m][nt][0], D[m][nt][1],
                           A[m][0][0], A[m][0][1], A[m][0][2], A[m][0][3], b0a, b1a);
                    mmaf16(D[m][nt][0], D[m][nt][1],
                           A[m][1][0], A[m][1][1], A[m][1][2], A[m][1][3], b0b, b1b);
                }
            }
        }

        __half* base = g_xp + (size_t)(dir * TLEN + t) * 16 * GDIM * 8;
        #pragma unroll
        for (int m = 0; m < 2; ++m) {
            const int gg0 = gtile * 128 + gbase + m * 16 + row;
            #pragma unroll
            for (int nt = 0; nt < 8; ++nt) {
                const int slice = wb * 8 + nt;
                __half* o = base + ((size_t)slice * GDIM) * 8 + kq;
                *(unsigned*)(o + (size_t)gg0 * 8)       = D[m][nt][0];
                *(unsigned*)(o + (size_t)(gg0 + 8) * 8) = D[m][nt][1];
            }
        }

        __threadfence();
        __syncthreads();
        if (tid == 0) atomicAdd(&g_flagc[dir][t >> 3], 1);
        return;
    }

    // ================= SCAN ROLE =================
    {
        __half* Wsm = (__half*)dynsm;   // [512][136]
        __shared__ __align__(16) __half h_pp[2][HDIM][8];

        const int dir   = bid >> 4;
        const int slice = bid & 15;
        const float* Whh = dir ? Whh_b : Whh_f;

        #pragma unroll 4
        for (int it = 0; it < 64; ++it) {
            const int idx = it * 256 + tid;
            const int rw = idx >> 5, q = idx & 31;
            const float4 v = __ldg((const float4*)(Whh + (size_t)rw * HDIM) + q);
            *(uint2*)&Wsm[rw * SC_WSTRIDE + q * 4] =
                make_uint2(pkh2(v.x, v.y), pkh2(v.z, v.w));
        }
        for (int i = tid; i < 2 * HDIM * 8; i += 256) ((__half*)h_pp)[i] = __float2half(0.f);
        __syncthreads();

        const int li = lane & 7, grp = lane >> 3;
        unsigned A[4][8][4];
        #pragma unroll
        for (int q = 0; q < 4; ++q) {
            const unsigned base = sptr(Wsm) +
                (((q * 128 + w * 16 + (grp & 1) * 8 + li) * SC_WSTRIDE + (grp >> 1) * 8) << 1);
            #pragma unroll
            for (int kt = 0; kt < 8; ++kt)
                ldsm4(A[q][kt][0], A[q][kt][1], A[q][kt][2], A[q][kt][3], base + kt * 32);
        }

        const int ur = w * 16 + (lane >> 2);
        const int cb = (lane & 3) * 2;
        const __half* xpd = g_xp + (size_t)dir * TLEN * 16 * GDIM * 8;
        size_t off[4];
        #pragma unroll
        for (int q = 0; q < 4; ++q)
            off[q] = ((size_t)slice * GDIM + q * 128 + ur) * 8 + cb;

        while (ld_acq(&g_flagc[dir][0]) < 32) __nanosleep(200);

        unsigned px0[4], px1[4];
        #pragma unroll
        for (int q = 0; q < 4; ++q) {
            px0[q] = *(const unsigned*)(xpd + off[q]);
            px1[q] = *(const unsigned*)(xpd + off[q] + 64);
        }

        unsigned c20 = 0u, c21 = 0u;
        unsigned hm0 = 0xFC00FC00u, hm1 = 0xFC00FC00u;

        #define GATE_MMA(q, p0, p1) do {                                          \
            unsigned d0 = px0c[q], d1 = px1c[q], e0 = 0u, e1 = 0u;                \
            _Pragma("unroll")                                                     \
            for (int kt = 0; kt < 4; ++kt) {                                      \
                mmaf16(d0, d1, A[q][kt][0], A[q][kt][1], A[q][kt][2], A[q][kt][3],\
                       B[kt][0], B[kt][1]);                                       \
                mmaf16(e0, e1, A[q][kt+4][0], A[q][kt+4][1], A[q][kt+4][2],       \
                       A[q][kt+4][3], B[kt+4][0], B[kt+4][1]);                    \
            }                                                                     \
            p0 = hadd2u(d0, e0); p1 = hadd2u(d1, e1);                             \
        } while (0)

        for (int t = 0; t < TLEN; ++t) {
            if ((t & 15) == 0 && slice == 0 && tid == 0)
                *(volatile int*)&g_prog[dir] = t >> 3;

            // gate the next 8t chunk every 8th step (single acquire load)
            if ((t & 7) == 0 && (t >> 3) + 1 < TLEN / 8) {
                const int* fp = &g_flagc[dir][(t >> 3) + 1];
                while (ld_acq(fp) < 32) __nanosleep(200);
            }

            unsigned B[8][2];
            const unsigned hbase = sptr(&h_pp[t & 1][0][0]) + lane * 16;
            #pragma unroll
            for (int j = 0; j < 4; ++j)
                ldsm4t(B[2*j][0], B[2*j][1], B[2*j+1][0], B[2*j+1][1], hbase + j * 512);

            unsigned px0c[4], px1c[4];
            #pragma unroll
            for (int q = 0; q < 4; ++q) { px0c[q] = px0[q]; px1c[q] = px1[q]; }

            const __half* xn = xpd + (size_t)((t + 1 < TLEN) ? t + 1 : t) * 16 * GDIM * 8;
            #pragma unroll
            for (int q = 0; q < 4; ++q) {
                px0[q] = *(const unsigned*)(xn + off[q]);
                px1[q] = *(const unsigned*)(xn + off[q] + 64);
            }

            // gate-sequential: each gate's activation hides under next gate's mma
            unsigned p0, p1;
            GATE_MMA(2, p0, p1);                       // g first
            const unsigned G0 = htanh2(p0), G1 = htanh2(p1);
            GATE_MMA(0, p0, p1);                       // i
            const unsigned I0 = hsig2(p0), I1 = hsig2(p1);
            GATE_MMA(1, p0, p1);                       // f
            const unsigned F0 = hsig2(p0), F1 = hsig2(p1);
            c20 = hfma2(F0, c20, hmul2(I0, G0));       // c + tanh(c) hide under o's mma
            c21 = hfma2(F1, c21, hmul2(I1, G1));
            const unsigned T0 = htanh2(c20), T1 = htanh2(c21);
            GATE_MMA(3, p0, p1);                       // o
            const unsigned O0 = hsig2(p0), O1 = hsig2(p1);
            const unsigned H0 = hmul2(O0, T0);
            const unsigned H1 = hmul2(O1, T1);

            __half* hw = &h_pp[(t + 1) & 1][0][0];
            *(unsigned*)&hw[ur * 8 + cb]       = H0;
            *(unsigned*)&hw[(ur + 8) * 8 + cb] = H1;
            hm0 = hmax2u(hm0, H0);                     // off the barrier path
            hm1 = hmax2u(hm1, H1);
            __syncthreads();
        }
        #undef GATE_MMA

        const float2 m0 = h22f2(hm0), m1 = h22f2(hm1);
        const int bb = slice * 8;
        g_pool[((size_t)dir * BATCH + bb + cb)     * HDIM + ur]     = m0.x;
        g_pool[((size_t)dir * BATCH + bb + cb + 1) * HDIM + ur]     = m0.y;
        g_pool[((size_t)dir * BATCH + bb + cb)     * HDIM + ur + 8] = m1.x;
        g_pool[((size_t)dir * BATCH + bb + cb + 1) * HDIM + ur + 8] = m1.y;
    }
}

// =====================================================================
// Kernel 2: MLP head + flag reset for next replay (graph-replay safe:
// globals start zeroed; every launch ends with flags reset).
// =====================================================================
__global__ void __launch_bounds__(256) mlp_kernel(
    const float* __restrict__ W1, const float* __restrict__ b1,
    const float* __restrict__ W2, const float* __restrict__ b2,
    float* __restrict__ out)
{
    __shared__ __align__(16) float pv[256];
    __shared__ float red[64];
    const int b = blockIdx.x;
    const int tid = threadIdx.x;
    const int u = tid >> 2, p = tid & 3;

    if (b == 0) {                       // reset sync state for next replay
        if (tid < 128) ((int*)g_flagc)[tid] = 0;   // 2*64 ints
        if (tid < 2) g_prog[tid] = 0;
    }

    {
        const int dir = tid >> 7, uu = tid & 127;
        pv[tid] = g_pool[((size_t)dir * BATCH + b) * HDIM + uu];
    }
    __syncthreads();

    float acc = 0.f;
    const float4* w4 = (const float4*)(W1 + (size_t)u * 256 + p * 64);
    const float4* p4 = (const float4*)(pv + p * 64);
    #pragma unroll
    for (int k = 0; k < 16; ++k) {
        const float4 wv = w4[k], pvv = p4[k];
        acc += wv.x * pvv.x + wv.y * pvv.y + wv.z * pvv.z + wv.w * pvv.w;
    }
    acc += __shfl_down_sync(0xffffffffu, acc, 2, 4);
    acc += __shfl_down_sync(0xffffffffu, acc, 1, 4);
    if (p == 0) red[u] = fmaxf(acc + b1[u], 0.f) * W2[u];
    __syncthreads();

    if (tid < 32) {
        float s = red[tid] + red[tid + 32];
        #pragma unroll
        for (int d = 16; d > 0; d >>= 1) s += __shfl_down_sync(0xffffffffu, s, d);
        if (tid == 0) out[b] = 1.f / (1.f + expf(-(s + b2[0])));
    }
}

// =====================================================================
extern "C" void kernel_launch(void* const* d_in, const int* in_sizes, int n_in,
                              void* d_out, int out_size) {
    const int*   x     = (const int*)d_in[0];
    const float* table = (const float*)d_in[1];
    const float* Wih_f = (const float*)d_in[2];
    const float* Whh_f = (const float*)d_in[3];
    const float* bih_f = (const float*)d_in[4];
    const float* bhh_f = (const float*)d_in[5];
    const float* Wih_b = (const float*)d_in[6];
    const float* Whh_b = (const float*)d_in[7];
    const float* bih_b = (const float*)d_in[8];
    const float* bhh_b = (const float*)d_in[9];
    const float* W1    = (const float*)d_in[10];
    const float* b1    = (const float*)d_in[11];
    const float* W2    = (const float*)d_in[12];
    const float* b2    = (const float*)d_in[13];
    float* out = (float*)d_out;

    cudaFuncSetAttribute(mega_kernel, cudaFuncAttributeMaxDynamicSharedMemorySize, SC_SMEM);

    mega_kernel<<<32 + 4096, 256, SC_SMEM>>>(x, table, Wih_f, Wih_b, Whh_f, Whh_b,
                                             bih_f, bhh_f, bih_b, bhh_b);
    mlp_kernel<<<128, 256>>>(W1, b1, W2, b2, out);
}